// round 15
// baseline (speedup 1.0000x reference)
#include <cuda_runtime.h>
#include <math.h>

// YearOperatorRouter: per-sample routed 3x3 edge magnitude.
// kx = [[-p,0,p],[-q,0,q],[-p,0,p]], ky = kx^T; out = sqrt(gx^2+gy^2+eps)*s, zero pad.
//
// R15 = R14 (rolling window, one-deep pipeline, sqrt.approx MUFU, folded s,
// __stcs stores) with the register footprint trimmed for occupancy:
//   - only the float4 of the next row is staged; the two halo scalars are
//     loaded at commit time (their 128B lines were fetched by the neighbor
//     lanes' staged float4s one iteration earlier -> guaranteed L1 hits)
//   - __launch_bounds__(128, 12): 12 blocks/SM (48 warps, 75% occ) needs
//     regs <= 42.

#define W 256
#define H 256
#define RPT 8   // output rows per thread

__device__ __forceinline__ float sqrt_approx(float a) {
    float r;
    asm("sqrt.approx.f32 %0, %1;" : "=f"(r) : "f"(a));
    return r;
}

__global__ __launch_bounds__(128, 12)
void year_router_kernel(const float* __restrict__ x,
                        const float* __restrict__ alpha,
                        const float* __restrict__ scale,
                        const int*   __restrict__ year,
                        float* __restrict__ out,
                        int C)
{
    const int x0 = threadIdx.x * 4;                          // 0..252 (blockDim.x = 64)
    const int y0 = (blockIdx.y * 2 + threadIdx.y) * RPT;     // blockDim.y = 2
    const int bc = blockIdx.z;

    // ---- per-sample operator parameters (uniform per z-block), s folded ----
    const int yr = __ldg(year + bc / C);
    float p, q, eps;
    if (yr == 2019) {            // sobel
        p = 1.0f; q = 2.0f; eps = 1e-8f;
    } else if (yr == 2020) {     // scharr
        p = 3.0f; q = 10.0f; eps = 1e-8f;
    } else {                     // learnable: sigmoid mix / max|k| (= q term)
        float a  = 1.0f / (1.0f + expf(-__ldg(alpha)));
        float pm = 3.0f  - 2.0f * a;
        float qm = 10.0f - 8.0f * a;        // qm > pm > 0 for a in (0,1)
        float s  = 1.0f / (1.0f + expf(-__ldg(scale)));
        p = (pm / qm) * s;
        q = s;
        eps = 1e-6f * s * s;
    }

    const bool hasL = (x0 > 0);
    const bool hasR = (x0 + 4 < W);

    const float* __restrict__ base  = x   + (size_t)bc * (H * W);
    float*       __restrict__ obase = out + (size_t)bc * (H * W);

    // ---- prologue: rows y0-1 and y0 fully into the window ----
    float rows[3][6];
    if (y0 > 0) {
        const float* r = base + (size_t)(y0 - 1) * W;
        float4 m = __ldg(reinterpret_cast<const float4*>(r + x0));
        rows[0][0] = hasL ? __ldg(r + x0 - 1) : 0.0f;
        rows[0][1] = m.x; rows[0][2] = m.y; rows[0][3] = m.z; rows[0][4] = m.w;
        rows[0][5] = hasR ? __ldg(r + x0 + 4) : 0.0f;
    } else {
#pragma unroll
        for (int j = 0; j < 6; j++) rows[0][j] = 0.0f;
    }
    {
        const float* r = base + (size_t)y0 * W;
        float4 m = __ldg(reinterpret_cast<const float4*>(r + x0));
        rows[1][0] = hasL ? __ldg(r + x0 - 1) : 0.0f;
        rows[1][1] = m.x; rows[1][2] = m.y; rows[1][3] = m.z; rows[1][4] = m.w;
        rows[1][5] = hasR ? __ldg(r + x0 + 4) : 0.0f;
    }

    // stage ONLY the float4 of row y0+1 (always < H since y0 <= H-RPT)
    float4 nm = __ldg(reinterpret_cast<const float4*>(base + (size_t)(y0 + 1) * W + x0));

#pragma unroll
    for (int i = 0; i < RPT; i++) {
        const int yn = y0 + i + 1;           // row being committed
        const bool vn = (yn < H);
        const float* rp = base + (size_t)yn * W;

        // commit staged float4; halo scalars load here and L1-hit (their lines
        // were fetched by neighbor lanes' staged float4s last iteration)
        float* rn = rows[(i + 2) % 3];
        rn[1] = nm.x; rn[2] = nm.y; rn[3] = nm.z; rn[4] = nm.w;
        rn[0] = (hasL && vn) ? __ldg(rp + x0 - 1) : 0.0f;
        rn[5] = (hasR && vn) ? __ldg(rp + x0 + 4) : 0.0f;

        // stage the float4 of row y0+i+2 for the NEXT iteration
        if (i + 1 < RPT) {
            if (yn + 1 < H)
                nm = __ldg(reinterpret_cast<const float4*>(rp + W + x0));
            else
                nm = make_float4(0.f, 0.f, 0.f, 0.f);
        }

        const float* r0 = rows[(i + 0) % 3];   // y-1
        const float* r1 = rows[(i + 1) % 3];   // y
        const float* r2 = rn;                  // y+1

        // vertical diffs (shared across adjacent outputs)
        float d[6];
#pragma unroll
        for (int j = 0; j < 6; j++) d[j] = r2[j] - r0[j];

        float o[4];
#pragma unroll
        for (int j = 0; j < 4; j++) {
            float gx = fmaf(q, r1[j + 2] - r1[j],
                            p * ((r0[j + 2] - r0[j]) + (r2[j + 2] - r2[j])));
            float gy = fmaf(q, d[j + 1], p * (d[j] + d[j + 2]));
            float g2 = fmaf(gx, gx, fmaf(gy, gy, eps));
            o[j] = sqrt_approx(g2);            // single MUFU; g2 >= eps > 0
        }
        // evict-stream store: keep the input L2-resident across graph replays
        __stcs(reinterpret_cast<float4*>(obase + (size_t)(y0 + i) * W + x0),
               make_float4(o[0], o[1], o[2], o[3]));
    }
}

extern "C" void kernel_launch(void* const* d_in, const int* in_sizes, int n_in,
                              void* d_out, int out_size)
{
    const float* x     = (const float*)d_in[0];   // [B, C, 256, 256] f32
    const float* alpha = (const float*)d_in[1];   // scalar f32
    const float* scale = (const float*)d_in[2];   // [1] f32
    const int*   year  = (const int*)d_in[3];     // [B] int32
    float* out = (float*)d_out;

    const int B  = in_sizes[3];
    const int BC = in_sizes[0] / (H * W);
    const int C  = BC / B;

    dim3 block(64, 2, 1);                 // 128 threads: 64 x-tiles, 2 row-strips
    dim3 grid(1, H / (RPT * 2), BC);      // (1, 16, 288) = 4608 blocks

    year_router_kernel<<<grid, block>>>(x, alpha, scale, year, out, C);
}

// round 16
// speedup vs baseline: 1.0690x; 1.0690x over previous
#include <cuda_runtime.h>
#include <math.h>

// YearOperatorRouter: per-sample routed 3x3 edge magnitude.
// kx = [[-p,0,p],[-q,0,q],[-p,0,p]], ky = kx^T; out = sqrt(gx^2+gy^2+eps)*s, zero pad.
//
// R16 = R14 (rolling window, FULL one-deep staging of the next row — float4
// AND halo scalars, sqrt.approx single-MUFU magnitude, s folded into p/q/eps,
// __stcs streaming stores) + __launch_bounds__(128, 12): cap regs at 42 so 12
// blocks (48 warps) fit per SM instead of 11. R15 proved the staging must not
// be trimmed (halo-at-commit re-exposed the load->use chain); this buys the
// occupancy from ptxas instead.

#define W 256
#define H 256
#define RPT 8   // output rows per thread

__device__ __forceinline__ float sqrt_approx(float a) {
    float r;
    asm("sqrt.approx.f32 %0, %1;" : "=f"(r) : "f"(a));
    return r;
}

__global__ __launch_bounds__(128, 12)
void year_router_kernel(const float* __restrict__ x,
                        const float* __restrict__ alpha,
                        const float* __restrict__ scale,
                        const int*   __restrict__ year,
                        float* __restrict__ out,
                        int C)
{
    const int x0 = threadIdx.x * 4;                          // 0..252 (blockDim.x = 64)
    const int y0 = (blockIdx.y * 2 + threadIdx.y) * RPT;     // blockDim.y = 2
    const int bc = blockIdx.z;

    // ---- per-sample operator parameters (uniform per z-block), s folded ----
    const int yr = __ldg(year + bc / C);
    float p, q, eps;
    if (yr == 2019) {            // sobel
        p = 1.0f; q = 2.0f; eps = 1e-8f;
    } else if (yr == 2020) {     // scharr
        p = 3.0f; q = 10.0f; eps = 1e-8f;
    } else {                     // learnable: sigmoid mix / max|k| (= q term)
        float a  = 1.0f / (1.0f + expf(-__ldg(alpha)));
        float pm = 3.0f  - 2.0f * a;
        float qm = 10.0f - 8.0f * a;        // qm > pm > 0 for a in (0,1)
        float s  = 1.0f / (1.0f + expf(-__ldg(scale)));
        p = (pm / qm) * s;
        q = s;
        eps = 1e-6f * s * s;
    }

    const bool hasL = (x0 > 0);
    const bool hasR = (x0 + 4 < W);

    const float* __restrict__ base  = x   + (size_t)bc * (H * W);
    float*       __restrict__ obase = out + (size_t)bc * (H * W);

    // ---- prologue: rows y0-1 and y0 into the window ----
    float rows[3][6];
    if (y0 > 0) {
        const float* r = base + (size_t)(y0 - 1) * W;
        float4 m = __ldg(reinterpret_cast<const float4*>(r + x0));
        rows[0][0] = hasL ? __ldg(r + x0 - 1) : 0.0f;
        rows[0][1] = m.x; rows[0][2] = m.y; rows[0][3] = m.z; rows[0][4] = m.w;
        rows[0][5] = hasR ? __ldg(r + x0 + 4) : 0.0f;
    } else {
#pragma unroll
        for (int j = 0; j < 6; j++) rows[0][j] = 0.0f;
    }
    {
        const float* r = base + (size_t)y0 * W;
        float4 m = __ldg(reinterpret_cast<const float4*>(r + x0));
        rows[1][0] = hasL ? __ldg(r + x0 - 1) : 0.0f;
        rows[1][1] = m.x; rows[1][2] = m.y; rows[1][3] = m.z; rows[1][4] = m.w;
        rows[1][5] = hasR ? __ldg(r + x0 + 4) : 0.0f;
    }

    // stage row y0+1 IN FULL (always < H since y0 <= H-RPT)
    float4 nm; float nl, nr;
    {
        const float* r = base + (size_t)(y0 + 1) * W;
        nm = __ldg(reinterpret_cast<const float4*>(r + x0));
        nl = hasL ? __ldg(r + x0 - 1) : 0.0f;
        nr = hasR ? __ldg(r + x0 + 4) : 0.0f;
    }

#pragma unroll
    for (int i = 0; i < RPT; i++) {
        // commit staged row y0+i+1 into the window (pure register moves)
        float* rn = rows[(i + 2) % 3];
        rn[0] = nl; rn[1] = nm.x; rn[2] = nm.y; rn[3] = nm.z; rn[4] = nm.w; rn[5] = nr;

        // stage row y0+i+2 for the NEXT iteration — these LDGs fly over the
        // compute below instead of stalling the next iteration's front
        if (i + 1 < RPT) {
            const int yn2 = y0 + i + 2;
            if (yn2 < H) {
                const float* r = base + (size_t)yn2 * W;
                nm = __ldg(reinterpret_cast<const float4*>(r + x0));
                nl = hasL ? __ldg(r + x0 - 1) : 0.0f;
                nr = hasR ? __ldg(r + x0 + 4) : 0.0f;
            } else {
                nm = make_float4(0.f, 0.f, 0.f, 0.f); nl = 0.f; nr = 0.f;
            }
        }

        const float* r0 = rows[(i + 0) % 3];   // y-1
        const float* r1 = rows[(i + 1) % 3];   // y
        const float* r2 = rn;                  // y+1

        // vertical diffs (shared across adjacent outputs)
        float d[6];
#pragma unroll
        for (int j = 0; j < 6; j++) d[j] = r2[j] - r0[j];

        float o[4];
#pragma unroll
        for (int j = 0; j < 4; j++) {
            float gx = fmaf(q, r1[j + 2] - r1[j],
                            p * ((r0[j + 2] - r0[j]) + (r2[j + 2] - r2[j])));
            float gy = fmaf(q, d[j + 1], p * (d[j] + d[j + 2]));
            float g2 = fmaf(gx, gx, fmaf(gy, gy, eps));
            o[j] = sqrt_approx(g2);            // single MUFU; g2 >= eps > 0
        }
        // evict-stream store: keep the input L2-resident across graph replays
        __stcs(reinterpret_cast<float4*>(obase + (size_t)(y0 + i) * W + x0),
               make_float4(o[0], o[1], o[2], o[3]));
    }
}

extern "C" void kernel_launch(void* const* d_in, const int* in_sizes, int n_in,
                              void* d_out, int out_size)
{
    const float* x     = (const float*)d_in[0];   // [B, C, 256, 256] f32
    const float* alpha = (const float*)d_in[1];   // scalar f32
    const float* scale = (const float*)d_in[2];   // [1] f32
    const int*   year  = (const int*)d_in[3];     // [B] int32
    float* out = (float*)d_out;

    const int B  = in_sizes[3];
    const int BC = in_sizes[0] / (H * W);
    const int C  = BC / B;

    dim3 block(64, 2, 1);                 // 128 threads: 64 x-tiles, 2 row-strips
    dim3 grid(1, H / (RPT * 2), BC);      // (1, 16, 288) = 4608 blocks

    year_router_kernel<<<grid, block>>>(x, alpha, scale, year, out, C);
}